// round 8
// baseline (speedup 1.0000x reference)
#include <cuda_runtime.h>
#include <math.h>
#include <stdint.h>
#include <stddef.h>

#define BB 32
#define SS 128
#define HH 512
#define DD 512
#define VV 32000
#define FF 768
#define NG 2048          // 4*H
#define NSTEPS 129       // 1 image warm-up + 128 caption steps
#define ROWS_PAD 4224    // 33*128 >= 129*32

// ---------------- static device scratch (no dynamic allocation) ----------------
__device__ __align__(16) float d_Xall[ROWS_PAD * DD];   // per-step inputs x_t
__device__ __align__(16) float d_Ux  [ROWS_PAD * NG];   // x_t@Uh0 + cb0
__device__ __align__(16) float d_M   [DD * NG];         // Wxh0 @ Uh1
__device__ __align__(16) float d_Mp  [DD * NG];         // permuted [k][j*4+g]
__device__ __align__(16) float d_Wp0 [HH * NG];         // Wh0 permuted
__device__ __align__(16) float d_Wp1 [HH * NG];         // Wh1 permuted
__device__ __align__(16) float d_Wf  [DD * VV];         // Wxh1 @ Wc
__device__ __align__(16) float d_cb0 [NG];
__device__ __align__(16) float d_cb1p[NG];              // permuted bias for cell1
__device__ __align__(16) float d_bcf [VV];
__device__ __align__(16) float d_h0  [2][BB * HH];
__device__ __align__(16) float d_h1  [2][BB * HH];
__device__ __align__(16) float d_c0  [BB * HH];
__device__ __align__(16) float d_c1  [BB * HH];
__device__ __align__(16) float d_Hs  [SS * BB * HH];    // layer-1 h per caption step

// ---------------- setup kernels -------------------------------------------------

__global__ void k_init(const float* __restrict__ h0, const float* __restrict__ c0) {
    int i = blockIdx.x * 256 + threadIdx.x;          // 16384
    d_h0[0][i] = h0[i];
    d_h1[0][i] = h0[BB * HH + i];
    d_c0[i]    = c0[i];
    d_c1[i]    = c0[BB * HH + i];
}

__global__ void k_ximg(const float* __restrict__ im, const float* __restrict__ Wim,
                       const float* __restrict__ bim) {
    int idx = blockIdx.x * 256 + threadIdx.x;        // 16384 = 32*512
    int b = idx >> 9, d = idx & 511;
    float s = bim[d];
    const float* ip = im + b * FF;
    #pragma unroll 4
    for (int k = 0; k < FF; k++) s += ip[k] * Wim[k * DD + d];
    d_Xall[b * DD + d] = s;                          // rows 0..31 = y_im
}

__global__ void k_gather(const int* __restrict__ tok, const float* __restrict__ embed) {
    int r = blockIdx.x;                              // 0..4095 : r = s*32+b
    int s = r >> 5, b = r & 31;
    int t = tok[b * SS + s];
    const float4* src = (const float4*)(embed + (size_t)t * DD);
    float4* dst = (float4*)(d_Xall + (size_t)(BB + r) * DD);
    dst[threadIdx.x] = src[threadIdx.x];             // 128 threads * float4 = 512
}

__global__ void k_zero_pad() {
    int i = blockIdx.x * 256 + threadIdx.x;          // 96*512 = 49152
    d_Xall[NSTEPS * BB * DD + i] = 0.f;
}

__global__ void k_cb0(const float* __restrict__ bw, const float* __restrict__ bu) {
    int n = blockIdx.x * 256 + threadIdx.x;          // 2048
    d_cb0[n] = bw[n] + bu[n];
}

// cb1p[j*4+g] = bw1 + bu1 + bxh0 @ Uh1  (permuted gate layout)
__global__ void k_cb1p(const float* __restrict__ bw, const float* __restrict__ bu,
                       const float* __restrict__ bxh, const float* __restrict__ Uh) {
    int n = blockIdx.x * 256 + threadIdx.x;          // 2048
    int g = n & 3, j = n >> 2;
    int col = g * HH + j;
    float s = bw[NG + col] + bu[NG + col];
    const float* U1 = Uh + (size_t)HH * NG;          // layer 1
    #pragma unroll 4
    for (int k = 0; k < DD; k++) s += bxh[k] * U1[(size_t)k * NG + col];
    d_cb1p[n] = s;
}

__global__ void k_bcf(const float* __restrict__ bc, const float* __restrict__ bxh,
                      const float* __restrict__ Wc) {
    int n = blockIdx.x * 256 + threadIdx.x;          // 32000 = 125*256
    float s = bc[n];
    const float* bx1 = bxh + DD;                     // layer 1
    #pragma unroll 4
    for (int k = 0; k < DD; k++) s += bx1[k] * Wc[(size_t)k * VV + n];
    d_bcf[n] = s;
}

// Wp[k*2048 + j*4 + g] = W[k*2048 + g*512 + j]
__global__ void k_permW(const float* __restrict__ W, float* __restrict__ Wp) {
    int idx = blockIdx.x * 256 + threadIdx.x;        // 1048576 = 4096*256
    int k = idx >> 11;
    int rest = idx & 2047;
    int j = rest >> 2, g = rest & 3;
    Wp[idx] = W[(size_t)k * NG + g * HH + j];
}

// ---------------- generic fp32 SGEMM: C[M,N] = A[M,K] @ B[K,N] (+bias) ----------
// 128x128 tile, BK=8, 256 threads, 8x8 per thread, double-buffered smem.
// remap!=0: Hs row r=(s*32+b) writes to output row (b*128+s) (classifier).
__global__ __launch_bounds__(256) void k_sgemm(
    const float* __restrict__ A, const float* __restrict__ Bm, float* __restrict__ C,
    int N, int K, const float* __restrict__ bias, int remap)
{
    __shared__ __align__(16) float As[2][8][132];
    __shared__ __align__(16) float Bs[2][8][128];
    int tid = threadIdx.x;
    int bm = blockIdx.y * 128, bn = blockIdx.x * 128;
    int arow = tid >> 1, akq = (tid & 1) * 4;
    int brow = tid >> 5, bcol = (tid & 31) * 4;
    int tx = tid & 15, ty = tid >> 4;
    float acc[8][8];
    #pragma unroll
    for (int i = 0; i < 8; i++)
        #pragma unroll
        for (int j = 0; j < 8; j++) acc[i][j] = 0.f;

    const float* Ap = A + (size_t)(bm + arow) * K + akq;
    const float* Bp = Bm + (size_t)brow * N + bn + bcol;

    {   // preload tile 0 into buffer 0
        float4 av = *(const float4*)Ap;
        float4 bv = *(const float4*)Bp;
        As[0][akq + 0][arow] = av.x; As[0][akq + 1][arow] = av.y;
        As[0][akq + 2][arow] = av.z; As[0][akq + 3][arow] = av.w;
        *(float4*)&Bs[0][brow][bcol] = bv;
    }
    __syncthreads();

    int ntiles = K >> 3;
    for (int t = 0; t < ntiles; t++) {
        int cur = t & 1;
        float4 av, bv;
        bool more = (t + 1 < ntiles);
        if (more) {
            av = *(const float4*)(Ap + (t + 1) * 8);
            bv = *(const float4*)(Bp + (size_t)(t + 1) * 8 * N);
        }
        #pragma unroll
        for (int kk = 0; kk < 8; kk++) {
            float a[8], b[8];
            *(float4*)(a)     = *(const float4*)&As[cur][kk][ty * 8];
            *(float4*)(a + 4) = *(const float4*)&As[cur][kk][ty * 8 + 4];
            *(float4*)(b)     = *(const float4*)&Bs[cur][kk][tx * 8];
            *(float4*)(b + 4) = *(const float4*)&Bs[cur][kk][tx * 8 + 4];
            #pragma unroll
            for (int i = 0; i < 8; i++)
                #pragma unroll
                for (int j = 0; j < 8; j++) acc[i][j] += a[i] * b[j];
        }
        if (more) {
            int nxt = cur ^ 1;
            As[nxt][akq + 0][arow] = av.x; As[nxt][akq + 1][arow] = av.y;
            As[nxt][akq + 2][arow] = av.z; As[nxt][akq + 3][arow] = av.w;
            *(float4*)&Bs[nxt][brow][bcol] = bv;
        }
        __syncthreads();
    }

    float bvals[8];
    #pragma unroll
    for (int j = 0; j < 8; j++) bvals[j] = bias ? bias[bn + tx * 8 + j] : 0.f;
    #pragma unroll
    for (int i = 0; i < 8; i++) {
        int r = bm + ty * 8 + i;
        size_t rowoff;
        if (remap) { int s = r >> 5; int b = r & 31; rowoff = (size_t)(b * SS + s) * N; }
        else rowoff = (size_t)r * N;
        float4 v0, v1;
        v0.x = acc[i][0] + bvals[0]; v0.y = acc[i][1] + bvals[1];
        v0.z = acc[i][2] + bvals[2]; v0.w = acc[i][3] + bvals[3];
        v1.x = acc[i][4] + bvals[4]; v1.y = acc[i][5] + bvals[5];
        v1.z = acc[i][6] + bvals[6]; v1.w = acc[i][7] + bvals[7];
        *(float4*)(C + rowoff + bn + tx * 8)     = v0;
        *(float4*)(C + rowoff + bn + tx * 8 + 4) = v1;
    }
}

// ---------------- fused LSTM cell kernels ---------------------------------------
// 16384 threads = 128 blocks x 128 threads. Thread (b, j) computes all 4 gates.
// Weights pre-permuted so one float4 load yields (f,i,o,cc) for (k, j).

__global__ __launch_bounds__(128) void k_cell0(int ping, int step) {
    __shared__ float hs[HH];
    int idx = blockIdx.x * 128 + threadIdx.x;
    int b = idx >> 9, j = idx & 511;                 // b constant within block
    const float* hin = d_h0[ping];
    for (int i = threadIdx.x; i < HH; i += 128) hs[i] = hin[b * HH + i];
    __syncthreads();

    const float* ux = d_Ux + ((size_t)step * BB + b) * NG;
    float gf = ux[j], gi = ux[HH + j], go = ux[2 * HH + j], gc = ux[3 * HH + j];

    const float4* wp = (const float4*)d_Wp0 + j;     // stride 512 float4 per k
    #pragma unroll 8
    for (int k = 0; k < HH; k++) {
        float hv = hs[k];
        float4 w = wp[(size_t)k * 512];
        gf += hv * w.x; gi += hv * w.y; go += hv * w.z; gc += hv * w.w;
    }

    float f  = 1.f / (1.f + expf(-gf));
    float ii = 1.f / (1.f + expf(-gi));
    float o  = 1.f / (1.f + expf(-go));
    float c  = d_c0[b * HH + j];
    float cn = f * c + ii * tanhf(gc);
    d_c0[b * HH + j] = cn;
    d_h0[ping ^ 1][b * HH + j] = o * tanhf(cn);
}

__global__ __launch_bounds__(128) void k_cell1(int ping, int step) {
    __shared__ float h1s[HH];
    __shared__ float h0s[HH];
    int idx = blockIdx.x * 128 + threadIdx.x;
    int b = idx >> 9, j = idx & 511;
    const float* h1in = d_h1[ping];
    const float* h0n  = d_h0[ping ^ 1];              // new h0 from this step's cell0
    for (int i = threadIdx.x; i < HH; i += 128) {
        h1s[i] = h1in[b * HH + i];
        h0s[i] = h0n[b * HH + i];
    }
    __syncthreads();

    float4 cb = *((const float4*)d_cb1p + j);
    float gf = cb.x, gi = cb.y, go = cb.z, gc = cb.w;

    const float4* wp = (const float4*)d_Wp1 + j;
    const float4* mp = (const float4*)d_Mp  + j;
    #pragma unroll 4
    for (int k = 0; k < HH; k++) {
        float hv = h1s[k];
        float xv = h0s[k];
        float4 w = wp[(size_t)k * 512];
        float4 m = mp[(size_t)k * 512];
        gf += hv * w.x + xv * m.x;
        gi += hv * w.y + xv * m.y;
        go += hv * w.z + xv * m.z;
        gc += hv * w.w + xv * m.w;
    }

    float f  = 1.f / (1.f + expf(-gf));
    float ii = 1.f / (1.f + expf(-gi));
    float o  = 1.f / (1.f + expf(-go));
    float c  = d_c1[b * HH + j];
    float cn = f * c + ii * tanhf(gc);
    d_c1[b * HH + j] = cn;
    float hn = o * tanhf(cn);
    d_h1[ping ^ 1][b * HH + j] = hn;
    if (step >= 1)                                   // caption steps only
        d_Hs[((size_t)(step - 1) * BB + b) * HH + j] = hn;
}

// ---------------- launch --------------------------------------------------------

extern "C" void kernel_launch(void* const* d_in, const int* in_sizes, int n_in,
                              void* d_out, int out_size) {
    const float* im    = (const float*)d_in[0];
    const int*   tok   = (const int*)  d_in[1];
    const float* h0    = (const float*)d_in[2];
    const float* c0    = (const float*)d_in[3];
    const float* embed = (const float*)d_in[4];
    const float* W_im  = (const float*)d_in[5];
    const float* b_im  = (const float*)d_in[6];
    const float* Wh    = (const float*)d_in[7];
    const float* bw    = (const float*)d_in[8];
    const float* Uh    = (const float*)d_in[9];
    const float* bu    = (const float*)d_in[10];
    const float* Wxh   = (const float*)d_in[11];
    const float* bxh   = (const float*)d_in[12];
    const float* Wc    = (const float*)d_in[13];
    const float* bc    = (const float*)d_in[14];
    float* out = (float*)d_out;

    float *pXall, *pUx, *pM, *pMp, *pWp0, *pWp1, *pWf, *pcb0, *pbcf, *pHs;
    cudaGetSymbolAddress((void**)&pXall, d_Xall);
    cudaGetSymbolAddress((void**)&pUx,   d_Ux);
    cudaGetSymbolAddress((void**)&pM,    d_M);
    cudaGetSymbolAddress((void**)&pMp,   d_Mp);
    cudaGetSymbolAddress((void**)&pWp0,  d_Wp0);
    cudaGetSymbolAddress((void**)&pWp1,  d_Wp1);
    cudaGetSymbolAddress((void**)&pWf,   d_Wf);
    cudaGetSymbolAddress((void**)&pcb0,  d_cb0);
    cudaGetSymbolAddress((void**)&pbcf,  d_bcf);
    cudaGetSymbolAddress((void**)&pHs,   d_Hs);

    // ---- setup (parallel, off critical path) ----
    k_init  <<<64, 256>>>(h0, c0);
    k_ximg  <<<64, 256>>>(im, W_im, b_im);
    k_gather<<<4096, 128>>>(tok, embed);
    k_zero_pad<<<192, 256>>>();
    k_cb0   <<<8, 256>>>(bw, bu);
    k_cb1p  <<<8, 256>>>(bw, bu, bxh, Uh);
    k_bcf   <<<125, 256>>>(bc, bxh, Wc);
    k_permW <<<4096, 256>>>(Wh, pWp0);
    k_permW <<<4096, 256>>>(Wh + (size_t)HH * NG, pWp1);

    // M = Wxh0 @ Uh1  [512,512] @ [512,2048]
    k_sgemm<<<dim3(16, 4), 256>>>(Wxh, Uh + (size_t)HH * NG, pM, NG, DD, nullptr, 0);
    k_permW<<<4096, 256>>>(pM, pMp);

    // Ux = Xall @ Uh0 + cb0   [4224,512] @ [512,2048]
    k_sgemm<<<dim3(16, 33), 256>>>(pXall, Uh, pUx, NG, DD, pcb0, 0);

    // Wf = Wxh1 @ Wc  [512,512] @ [512,32000]
    k_sgemm<<<dim3(250, 4), 256>>>(Wxh + (size_t)HH * DD, Wc, pWf, VV, DD, nullptr, 0);

    // ---- sequential recurrence: 129 steps x 2 fused cell kernels ----
    for (int t = 0; t < NSTEPS; t++) {
        int ping = t & 1;
        k_cell0<<<128, 128>>>(ping, t);
        k_cell1<<<128, 128>>>(ping, t);
    }

    // ---- classifier: logits = Hs @ Wf + bcf  [4096,512] @ [512,32000] ----
    k_sgemm<<<dim3(250, 32), 256>>>(pHs, pWf, out, VV, DD, pbcf, 1);
}

// round 10
// speedup vs baseline: 2.0000x; 2.0000x over previous
#include <cuda_runtime.h>
#include <cuda_bf16.h>
#include <math.h>
#include <stdint.h>
#include <stddef.h>

#define BB 32
#define SS 128
#define HH 512
#define DD 512
#define VV 32000
#define FF 768
#define NG 2048          // 4*H
#define NSTEPS 129
#define ROWS_PAD 4224    // 132*32

// ---------------- static device scratch ----------------------------------------
__device__ __align__(16) float d_Xall[ROWS_PAD * DD];
__device__ __align__(16) float d_Uxp [ROWS_PAD * NG];     // [step][col][b] permuted
__device__ __align__(16) float d_M   [DD * NG];
__device__ __align__(16) float d_Mp  [DD * NG];
__device__ __align__(16) float d_Up0 [DD * NG];           // Uh0 permuted
__device__ __align__(16) float d_Wp0 [HH * NG];
__device__ __align__(16) float d_Wp1 [HH * NG];
__device__ __align__(16) float d_Wf  [DD * VV];           // Wxh1 @ Wc (fp32)
__device__ __align__(16) __nv_bfloat16 d_WfTh[VV * DD];   // Wf^T hi  [n][k]
__device__ __align__(16) __nv_bfloat16 d_WfTl[VV * DD];   // Wf^T lo
__device__ __align__(16) __nv_bfloat16 d_Hh[BB * SS * HH];// Hs hi [b*128+s][k]
__device__ __align__(16) __nv_bfloat16 d_Hl[BB * SS * HH];
__device__ __align__(16) float d_cb0p[NG];
__device__ __align__(16) float d_cb1p[NG];
__device__ __align__(16) float d_bcf [VV];
__device__ __align__(16) float d_h0T [2][HH * BB];        // transposed [j][b]
__device__ __align__(16) float d_h1T [2][HH * BB];
__device__ __align__(16) float d_c0T [HH * BB];
__device__ __align__(16) float d_c1T [HH * BB];

// ---------------- setup kernels -------------------------------------------------

__global__ void k_init(const float* __restrict__ h0, const float* __restrict__ c0) {
    int i = blockIdx.x * 256 + threadIdx.x;          // 16384
    int b = i & 31, j = i >> 5;
    d_h0T[0][j * BB + b] = h0[b * HH + j];
    d_h1T[0][j * BB + b] = h0[BB * HH + b * HH + j];
    d_c0T[j * BB + b]    = c0[b * HH + j];
    d_c1T[j * BB + b]    = c0[BB * HH + b * HH + j];
}

__global__ void k_ximg(const float* __restrict__ im, const float* __restrict__ Wim,
                       const float* __restrict__ bim) {
    int idx = blockIdx.x * 256 + threadIdx.x;        // 16384
    int b = idx >> 9, d = idx & 511;
    float s = bim[d];
    const float* ip = im + b * FF;
    #pragma unroll 4
    for (int k = 0; k < FF; k++) s += ip[k] * Wim[k * DD + d];
    d_Xall[b * DD + d] = s;
}

__global__ void k_gather(const int* __restrict__ tok, const float* __restrict__ embed) {
    int r = blockIdx.x;                              // s*32+b
    int s = r >> 5, b = r & 31;
    int t = tok[b * SS + s];
    const float4* src = (const float4*)(embed + (size_t)t * DD);
    float4* dst = (float4*)(d_Xall + (size_t)(BB + r) * DD);
    dst[threadIdx.x] = src[threadIdx.x];
}

__global__ void k_zero_pad() {
    int i = blockIdx.x * 256 + threadIdx.x;          // 49152
    d_Xall[NSTEPS * BB * DD + i] = 0.f;
}

__global__ void k_cb0p(const float* __restrict__ bw, const float* __restrict__ bu) {
    int n = blockIdx.x * 256 + threadIdx.x;          // 2048: n = j*4+g
    int g = n & 3, j = n >> 2;
    d_cb0p[n] = bw[g * HH + j] + bu[g * HH + j];
}

__global__ void k_cb1p(const float* __restrict__ bw, const float* __restrict__ bu,
                       const float* __restrict__ bxh, const float* __restrict__ Uh) {
    int n = blockIdx.x * 256 + threadIdx.x;          // 2048
    int g = n & 3, j = n >> 2;
    int col = g * HH + j;
    float s = bw[NG + col] + bu[NG + col];
    const float* U1 = Uh + (size_t)HH * NG;
    #pragma unroll 4
    for (int k = 0; k < DD; k++) s += bxh[k] * U1[(size_t)k * NG + col];
    d_cb1p[n] = s;
}

__global__ void k_bcf(const float* __restrict__ bc, const float* __restrict__ bxh,
                      const float* __restrict__ Wc) {
    int n = blockIdx.x * 256 + threadIdx.x;          // 32000
    float s = bc[n];
    const float* bx1 = bxh + DD;
    #pragma unroll 4
    for (int k = 0; k < DD; k++) s += bx1[k] * Wc[(size_t)k * VV + n];
    d_bcf[n] = s;
}

// Wp[k*2048 + j*4 + g] = W[k*2048 + g*512 + j]
__global__ void k_permW(const float* __restrict__ W, float* __restrict__ Wp) {
    int idx = blockIdx.x * 256 + threadIdx.x;        // 1048576
    int k = idx >> 11;
    int rest = idx & 2047;
    int j = rest >> 2, g = rest & 3;
    Wp[idx] = W[(size_t)k * NG + g * HH + j];
}

// transpose + hi/lo split of Wf: [512][32000] fp32 -> [32000][512] bf16 x2
__global__ void k_cvtWf() {
    __shared__ float ts[32][33];
    int n0 = blockIdx.x * 32, k0 = blockIdx.y * 32;
    int tx = threadIdx.x & 31, ty = threadIdx.x >> 5;   // 32 x 8
    #pragma unroll
    for (int i = 0; i < 4; i++)
        ts[ty + i * 8][tx] = d_Wf[(size_t)(k0 + ty + i * 8) * VV + n0 + tx];
    __syncthreads();
    #pragma unroll
    for (int i = 0; i < 4; i++) {
        int n = n0 + ty + i * 8, k = k0 + tx;
        float v = ts[tx][ty + i * 8];
        __nv_bfloat16 h = __float2bfloat16(v);
        d_WfTh[(size_t)n * DD + k] = h;
        d_WfTl[(size_t)n * DD + k] = __float2bfloat16(v - __bfloat162float(h));
    }
}

// ---------------- fp32 SGEMM (precompute only) ----------------------------------
// remap: 0 = row-major C; 2 = Ux permute: row r=(step*32+b) -> C[(step*N+col)*32+b]
__global__ __launch_bounds__(256) void k_sgemm(
    const float* __restrict__ A, const float* __restrict__ Bm, float* __restrict__ C,
    int N, int K, const float* __restrict__ bias, int remap)
{
    __shared__ __align__(16) float As[2][8][132];
    __shared__ __align__(16) float Bs[2][8][128];
    int tid = threadIdx.x;
    int bm = blockIdx.y * 128, bn = blockIdx.x * 128;
    int arow = tid >> 1, akq = (tid & 1) * 4;
    int brow = tid >> 5, bcol = (tid & 31) * 4;
    int tx = tid & 15, ty = tid >> 4;
    float acc[8][8];
    #pragma unroll
    for (int i = 0; i < 8; i++)
        #pragma unroll
        for (int j = 0; j < 8; j++) acc[i][j] = 0.f;

    const float* Ap = A + (size_t)(bm + arow) * K + akq;
    const float* Bp = Bm + (size_t)brow * N + bn + bcol;
    {
        float4 av = *(const float4*)Ap;
        float4 bv = *(const float4*)Bp;
        As[0][akq + 0][arow] = av.x; As[0][akq + 1][arow] = av.y;
        As[0][akq + 2][arow] = av.z; As[0][akq + 3][arow] = av.w;
        *(float4*)&Bs[0][brow][bcol] = bv;
    }
    __syncthreads();

    int ntiles = K >> 3;
    for (int t = 0; t < ntiles; t++) {
        int cur = t & 1;
        float4 av, bv;
        bool more = (t + 1 < ntiles);
        if (more) {
            av = *(const float4*)(Ap + (t + 1) * 8);
            bv = *(const float4*)(Bp + (size_t)(t + 1) * 8 * N);
        }
        #pragma unroll
        for (int kk = 0; kk < 8; kk++) {
            float a[8], b[8];
            *(float4*)(a)     = *(const float4*)&As[cur][kk][ty * 8];
            *(float4*)(a + 4) = *(const float4*)&As[cur][kk][ty * 8 + 4];
            *(float4*)(b)     = *(const float4*)&Bs[cur][kk][tx * 8];
            *(float4*)(b + 4) = *(const float4*)&Bs[cur][kk][tx * 8 + 4];
            #pragma unroll
            for (int i = 0; i < 8; i++)
                #pragma unroll
                for (int j = 0; j < 8; j++) acc[i][j] += a[i] * b[j];
        }
        if (more) {
            int nxt = cur ^ 1;
            As[nxt][akq + 0][arow] = av.x; As[nxt][akq + 1][arow] = av.y;
            As[nxt][akq + 2][arow] = av.z; As[nxt][akq + 3][arow] = av.w;
            *(float4*)&Bs[nxt][brow][bcol] = bv;
        }
        __syncthreads();
    }

    float bvals[8];
    #pragma unroll
    for (int j = 0; j < 8; j++) bvals[j] = bias ? bias[bn + tx * 8 + j] : 0.f;
    #pragma unroll
    for (int i = 0; i < 8; i++) {
        int r = bm + ty * 8 + i;
        if (remap == 2) {
            int st = r >> 5, bb = r & 31;
            #pragma unroll
            for (int jj = 0; jj < 8; jj++)
                C[((size_t)st * N + bn + tx * 8 + jj) * 32 + bb] = acc[i][jj] + bvals[jj];
        } else {
            size_t rowoff = (size_t)r * N;
            float4 v0, v1;
            v0.x = acc[i][0] + bvals[0]; v0.y = acc[i][1] + bvals[1];
            v0.z = acc[i][2] + bvals[2]; v0.w = acc[i][3] + bvals[3];
            v1.x = acc[i][4] + bvals[4]; v1.y = acc[i][5] + bvals[5];
            v1.z = acc[i][6] + bvals[6]; v1.w = acc[i][7] + bvals[7];
            *(float4*)(C + rowoff + bn + tx * 8)     = v0;
            *(float4*)(C + rowoff + bn + tx * 8 + 4) = v1;
        }
    }
}

// ---------------- LSTM cell kernels (weight-read-once) ---------------------------

__global__ __launch_bounds__(256) void k_cell0(int ping, int step) {
    __shared__ float red[8][512];
    int tid = threadIdx.x;
    int b = tid & 31, kc = tid >> 5;
    int C0 = blockIdx.x * 16;
    const float* hT = d_h0T[ping];
    const float4* wp4 = (const float4*)d_Wp0;
    float acc[16];
    #pragma unroll
    for (int c = 0; c < 16; c++) acc[c] = 0.f;

    int k0 = kc * 64;
    #pragma unroll 4
    for (int k = k0; k < k0 + 64; k++) {
        float hv = hT[k * BB + b];
        const float4* w = wp4 + (size_t)k * 512 + (C0 >> 2);
        float4 w0 = w[0], w1 = w[1], w2 = w[2], w3 = w[3];
        acc[0]  += hv * w0.x; acc[1]  += hv * w0.y; acc[2]  += hv * w0.z; acc[3]  += hv * w0.w;
        acc[4]  += hv * w1.x; acc[5]  += hv * w1.y; acc[6]  += hv * w1.z; acc[7]  += hv * w1.w;
        acc[8]  += hv * w2.x; acc[9]  += hv * w2.y; acc[10] += hv * w2.z; acc[11] += hv * w2.w;
        acc[12] += hv * w3.x; acc[13] += hv * w3.y; acc[14] += hv * w3.z; acc[15] += hv * w3.w;
    }
    #pragma unroll
    for (int c = 0; c < 16; c++) red[kc][c * 32 + b] = acc[c];
    __syncthreads();

    #pragma unroll
    for (int s = tid; s < 512; s += 256) {
        int c = s >> 5, bb = s & 31;
        float v = d_Uxp[((size_t)step * NG + C0 + c) * 32 + bb];
        #pragma unroll
        for (int q = 0; q < 8; q++) v += red[q][s];
        red[0][s] = v;
    }
    __syncthreads();

    if (tid < 128) {
        int bb = tid & 31, jl = tid >> 5;
        float gf = red[0][(jl * 4 + 0) * 32 + bb];
        float gi = red[0][(jl * 4 + 1) * 32 + bb];
        float go = red[0][(jl * 4 + 2) * 32 + bb];
        float gc = red[0][(jl * 4 + 3) * 32 + bb];
        float f  = 1.f / (1.f + expf(-gf));
        float ii = 1.f / (1.f + expf(-gi));
        float o  = 1.f / (1.f + expf(-go));
        int jg = blockIdx.x * 4 + jl;
        float c  = d_c0T[jg * 32 + bb];
        float cn = f * c + ii * tanhf(gc);
        d_c0T[jg * 32 + bb] = cn;
        d_h0T[ping ^ 1][jg * 32 + bb] = o * tanhf(cn);
    }
}

__global__ __launch_bounds__(256) void k_cell1(int ping, int step) {
    __shared__ float red[8][512];
    int tid = threadIdx.x;
    int b = tid & 31, kc = tid >> 5;
    int C0 = blockIdx.x * 16;
    const float* h1 = d_h1T[ping];
    const float* h0 = d_h0T[ping ^ 1];
    const float4* wp4 = (const float4*)d_Wp1;
    const float4* mp4 = (const float4*)d_Mp;
    float acc[16];
    #pragma unroll
    for (int c = 0; c < 16; c++) acc[c] = 0.f;

    int k0 = kc * 64;
    #pragma unroll 2
    for (int k = k0; k < k0 + 64; k++) {
        float hv = h1[k * BB + b];
        float xv = h0[k * BB + b];
        const float4* w = wp4 + (size_t)k * 512 + (C0 >> 2);
        const float4* m = mp4 + (size_t)k * 512 + (C0 >> 2);
        #pragma unroll
        for (int q = 0; q < 4; q++) {
            float4 wv = w[q], mv = m[q];
            acc[q * 4 + 0] += hv * wv.x + xv * mv.x;
            acc[q * 4 + 1] += hv * wv.y + xv * mv.y;
            acc[q * 4 + 2] += hv * wv.z + xv * mv.z;
            acc[q * 4 + 3] += hv * wv.w + xv * mv.w;
        }
    }
    #pragma unroll
    for (int c = 0; c < 16; c++) red[kc][c * 32 + b] = acc[c];
    __syncthreads();

    #pragma unroll
    for (int s = tid; s < 512; s += 256) {
        int c = s >> 5;
        float v = d_cb1p[C0 + c];
        #pragma unroll
        for (int q = 0; q < 8; q++) v += red[q][s];
        red[0][s] = v;
    }
    __syncthreads();

    if (tid < 128) {
        int bb = tid & 31, jl = tid >> 5;
        float gf = red[0][(jl * 4 + 0) * 32 + bb];
        float gi = red[0][(jl * 4 + 1) * 32 + bb];
        float go = red[0][(jl * 4 + 2) * 32 + bb];
        float gc = red[0][(jl * 4 + 3) * 32 + bb];
        float f  = 1.f / (1.f + expf(-gf));
        float ii = 1.f / (1.f + expf(-gi));
        float o  = 1.f / (1.f + expf(-go));
        int jg = blockIdx.x * 4 + jl;
        float c  = d_c1T[jg * 32 + bb];
        float cn = f * c + ii * tanhf(gc);
        d_c1T[jg * 32 + bb] = cn;
        float hn = o * tanhf(cn);
        d_h1T[ping ^ 1][jg * 32 + bb] = hn;
        if (step >= 1) {
            size_t row = (size_t)bb * SS + (step - 1);   // remapped for classifier
            __nv_bfloat16 hh = __float2bfloat16(hn);
            d_Hh[row * HH + jg] = hh;
            d_Hl[row * HH + jg] = __float2bfloat16(hn - __bfloat162float(hh));
        }
    }
}

// ---------------- HMMA classifier: out = Hs @ WfT^T + bcf ------------------------
// mma.sync.m16n8k16 bf16, 3-term split precision. CTA 128x128, 8 warps (4M x 2N),
// warp tile 32x64. smem rows padded to 40 bf16 (80B) -> conflict-free ldmatrix.

__device__ __forceinline__ uint32_t smem_u32(const void* p) {
    uint32_t a;
    asm("{ .reg .u64 t; cvta.to.shared.u64 t, %1; cvt.u32.u64 %0, t; }" : "=r"(a) : "l"(p));
    return a;
}

#define LDSM4(R0, R1, R2, R3, ADDR) \
    asm volatile("ldmatrix.sync.aligned.m8n8.x4.shared.b16 {%0,%1,%2,%3}, [%4];" \
                 : "=r"(R0), "=r"(R1), "=r"(R2), "=r"(R3) : "r"(ADDR))

#define MMA16816(C, A, B0, B1) \
    asm volatile("mma.sync.aligned.m16n8k16.row.col.f32.bf16.bf16.f32 " \
                 "{%0,%1,%2,%3}, {%4,%5,%6,%7}, {%8,%9}, {%0,%1,%2,%3};" \
                 : "+f"((C)[0]), "+f"((C)[1]), "+f"((C)[2]), "+f"((C)[3]) \
                 : "r"((A)[0]), "r"((A)[1]), "r"((A)[2]), "r"((A)[3]), "r"(B0), "r"(B1))

__global__ __launch_bounds__(256) void k_clf(float* __restrict__ out) {
    __shared__ __align__(16) __nv_bfloat16 sAh[128 * 40];
    __shared__ __align__(16) __nv_bfloat16 sAl[128 * 40];
    __shared__ __align__(16) __nv_bfloat16 sBh[128 * 40];
    __shared__ __align__(16) __nv_bfloat16 sBl[128 * 40];
    int tid = threadIdx.x;
    int lane = tid & 31, warp = tid >> 5;
    int n0 = blockIdx.x * 128, m0 = blockIdx.y * 128;
    int wm = (warp >> 1) * 32;       // 0..96
    int wn = (warp & 1) * 64;        // 0, 64

    float acc[2][8][4];
    #pragma unroll
    for (int i = 0; i < 2; i++)
        #pragma unroll
        for (int j = 0; j < 8; j++)
            #pragma unroll
            for (int q = 0; q < 4; q++) acc[i][j][q] = 0.f;

    int lrow = tid >> 1;             // 0..127
    int lq0 = (tid & 1) * 2;         // quad 0 or 2
    const uint4* gAh = (const uint4*)d_Hh   + (size_t)(m0 + lrow) * 64 + lq0;
    const uint4* gAl = (const uint4*)d_Hl   + (size_t)(m0 + lrow) * 64 + lq0;
    const uint4* gBh = (const uint4*)d_WfTh + (size_t)(n0 + lrow) * 64 + lq0;
    const uint4* gBl = (const uint4*)d_WfTl + (size_t)(n0 + lrow) * 64 + lq0;

    int r16 = lane & 15;
    uint32_t lmoff = (uint32_t)(r16 * 80 + (lane >> 4) * 16);
    uint32_t aAh = smem_u32(sAh) + lmoff, aAl = smem_u32(sAl) + lmoff;
    uint32_t aBh = smem_u32(sBh) + lmoff, aBl = smem_u32(sBl) + lmoff;

    for (int kc = 0; kc < 16; kc++) {
        if (kc) __syncthreads();
        #pragma unroll
        for (int i = 0; i < 2; i++) {
            *(uint4*)(sAh + lrow * 40 + (lq0 + i) * 8) = gAh[kc * 4 + i];
            *(uint4*)(sAl + lrow * 40 + (lq0 + i) * 8) = gAl[kc * 4 + i];
            *(uint4*)(sBh + lrow * 40 + (lq0 + i) * 8) = gBh[kc * 4 + i];
            *(uint4*)(sBl + lrow * 40 + (lq0 + i) * 8) = gBl[kc * 4 + i];
        }
        __syncthreads();
        #pragma unroll
        for (int k16 = 0; k16 < 2; k16++) {
            uint32_t kb = k16 * 32;
            uint32_t ah[2][4], al[2][4];
            #pragma unroll
            for (int mf = 0; mf < 2; mf++) {
                uint32_t off = (uint32_t)((wm + mf * 16) * 80) + kb;
                LDSM4(ah[mf][0], ah[mf][1], ah[mf][2], ah[mf][3], aAh + off);
                LDSM4(al[mf][0], al[mf][1], al[mf][2], al[mf][3], aAl + off);
            }
            #pragma unroll
            for (int g = 0; g < 4; g++) {
                uint32_t off = (uint32_t)((wn + g * 16) * 80) + kb;
                uint32_t bh0, bh1, bh2, bh3, bl0, bl1, bl2, bl3;
                LDSM4(bh0, bh1, bh2, bh3, aBh + off);
                LDSM4(bl0, bl1, bl2, bl3, aBl + off);
                #pragma unroll
                for (int mf = 0; mf < 2; mf++) {
                    MMA16816(acc[mf][g * 2],     ah[mf], bh0, bh2);
                    MMA16816(acc[mf][g * 2 + 1], ah[mf], bh1, bh3);
                    MMA16816(acc[mf][g * 2],     ah[mf], bl0, bl2);
                    MMA16816(acc[mf][g * 2 + 1], ah[mf], bl1, bl3);
                    MMA16816(acc[mf][g * 2],     al[mf], bh0, bh2);
                    MMA16816(acc[mf][g * 2 + 1], al[mf], bh1, bh3);
                }
            }
        }
    }

    #pragma unroll
    for (int mf = 0; mf < 2; mf++) {
        int m = m0 + wm + mf * 16 + (lane >> 2);
        float* o0 = out + (size_t)m * VV;
        float* o1 = out + (size_t)(m + 8) * VV;
        #pragma unroll
        for (int nf = 0; nf < 8; nf++) {
            int n = n0 + wn + nf * 8 + (lane & 3) * 2;
            float b0v = d_bcf[n], b1v = d_bcf[n + 1];
            float2 v0, v1;
            v0.x = acc[mf][nf][0] + b0v; v0.y = acc[mf][nf][1] + b1v;
            v1.x = acc[mf][nf][2] + b0v; v1.y = acc[mf][nf][3] + b1v;
            *(float2*)(o0 + n) = v0;
            *(float2*)(o1 + n) = v1;
        }
    }
}

// ---------------- launch --------------------------------------------------------

extern "C" void kernel_launch(void* const* d_in, const int* in_sizes, int n_in,
                              void* d_out, int out_size) {
    const float* im    = (const float*)d_in[0];
    const int*   tok   = (const int*)  d_in[1];
    const float* h0    = (const float*)d_in[2];
    const float* c0    = (const float*)d_in[3];
    const float* embed = (const float*)d_in[4];
    const float* W_im  = (const float*)d_in[5];
    const float* b_im  = (const float*)d_in[6];
    const float* Wh    = (const float*)d_in[7];
    const float* bw    = (const float*)d_in[8];
    const float* Uh    = (const float*)d_in[9];
    const float* bu    = (const float*)d_in[10];
    const float* Wxh   = (const float*)d_in[11];
    const float* bxh   = (const float*)d_in[12];
    const float* Wc    = (const float*)d_in[13];
    const float* bc    = (const float*)d_in[14];
    float* out = (float*)d_out;

    float *pXall, *pUxp, *pM, *pMp, *pUp0, *pWp0, *pWp1, *pWf, *pcb0p;
    cudaGetSymbolAddress((void**)&pXall, d_Xall);
    cudaGetSymbolAddress((void**)&pUxp,  d_Uxp);
    cudaGetSymbolAddress((void**)&pM,    d_M);
    cudaGetSymbolAddress((void**)&pMp,   d_Mp);
    cudaGetSymbolAddress((void**)&pUp0,  d_Up0);
    cudaGetSymbolAddress((void**)&pWp0,  d_Wp0);
    cudaGetSymbolAddress((void**)&pWp1,  d_Wp1);
    cudaGetSymbolAddress((void**)&pWf,   d_Wf);
    cudaGetSymbolAddress((void**)&pcb0p, d_cb0p);

    // ---- setup (off critical path) ----
    k_init    <<<64, 256>>>(h0, c0);
    k_ximg    <<<64, 256>>>(im, W_im, b_im);
    k_gather  <<<4096, 128>>>(tok, embed);
    k_zero_pad<<<192, 256>>>();
    k_cb0p    <<<8, 256>>>(bw, bu);
    k_cb1p    <<<8, 256>>>(bw, bu, bxh, Uh);
    k_bcf     <<<125, 256>>>(bc, bxh, Wc);
    k_permW   <<<4096, 256>>>(Wh, pWp0);
    k_permW   <<<4096, 256>>>(Wh + (size_t)HH * NG, pWp1);
    k_permW   <<<4096, 256>>>(Uh, pUp0);

    // M = Wxh0 @ Uh1, then permute
    k_sgemm<<<dim3(16, 4), 256>>>(Wxh, Uh + (size_t)HH * NG, pM, NG, DD, nullptr, 0);
    k_permW<<<4096, 256>>>(pM, pMp);

    // Uxp = Xall @ Up0 + cb0p, permuted-write [step][col][b]
    k_sgemm<<<dim3(16, 33), 256>>>(pXall, pUp0, pUxp, NG, DD, pcb0p, 2);

    // Wf = Wxh1 @ Wc (fp32), then transpose + bf16 hi/lo split
    k_sgemm<<<dim3(250, 4), 256>>>(Wxh + (size_t)HH * DD, Wc, pWf, VV, DD, nullptr, 0);
    k_cvtWf<<<dim3(1000, 16), 256>>>();

    // ---- sequential recurrence ----
    for (int t = 0; t < NSTEPS; t++) {
        int ping = t & 1;
        k_cell0<<<128, 256>>>(ping, t);
        k_cell1<<<128, 256>>>(ping, t);
    }

    // ---- classifier on tensor cores (mma.sync bf16, split precision) ----
    k_clf<<<dim3(250, 32), 256>>>(out);
}

// round 13
// speedup vs baseline: 3.3457x; 1.6728x over previous
#include <cuda_runtime.h>
#include <cuda_bf16.h>
#include <math.h>
#include <stdint.h>
#include <stddef.h>

#define BB 32
#define SS 128
#define HH 512
#define DD 512
#define VV 32000
#define FF 768
#define NG 2048          // 4*H
#define NSTEPS 129
#define ROWS_PAD 4224    // 132*32
#define RECUR_BLOCKS 128

// ---------------- static device scratch ----------------------------------------
__device__ __align__(16) float d_Xall[ROWS_PAD * DD];
__device__ __align__(16) float d_Uxp [ROWS_PAD * NG];     // [step][col][b]
__device__ __align__(16) float d_M   [DD * NG];
__device__ __align__(16) float d_Mp  [DD * NG];
__device__ __align__(16) float d_Up0 [DD * NG];
__device__ __align__(16) float d_Wp0 [HH * NG];
__device__ __align__(16) float d_Wp1 [HH * NG];
__device__ __align__(16) __nv_bfloat16 d_WcTh[VV * DD];   // Wc^T hi  [n][k]
__device__ __align__(16) __nv_bfloat16 d_WcTl[VV * DD];   // Wc^T lo
__device__ __align__(16) float d_Hs[BB * SS * HH];        // layer-1 h, row b*128+s
__device__ __align__(16) __nv_bfloat16 d_Ph[BB * SS * DD];// P hi [b*128+s][k]
__device__ __align__(16) __nv_bfloat16 d_Pl[BB * SS * DD];// P lo
__device__ __align__(16) float d_cb0p[NG];
__device__ __align__(16) float d_cb1p[NG];
__device__ __align__(16) float d_h0T [2][HH * BB];        // transposed [j][b]
__device__ __align__(16) float d_h1T [2][HH * BB];
__device__ __align__(16) float d_c0T [HH * BB];
__device__ __align__(16) float d_c1T [HH * BB];
__device__ unsigned d_bar_cnt;
__device__ unsigned d_bar_gen;

// ---------------- setup kernels -------------------------------------------------

__global__ void k_init(const float* __restrict__ h0, const float* __restrict__ c0) {
    int i = blockIdx.x * 256 + threadIdx.x;          // 16384
    int b = i & 31, j = i >> 5;
    d_h0T[0][j * BB + b] = h0[b * HH + j];
    d_h1T[0][j * BB + b] = h0[BB * HH + b * HH + j];
    d_c0T[j * BB + b]    = c0[b * HH + j];
    d_c1T[j * BB + b]    = c0[BB * HH + b * HH + j];
}

__global__ void k_ximg(const float* __restrict__ im, const float* __restrict__ Wim,
                       const float* __restrict__ bim) {
    int idx = blockIdx.x * 256 + threadIdx.x;        // 16384
    int b = idx >> 9, d = idx & 511;
    float s = bim[d];
    const float* ip = im + b * FF;
    #pragma unroll 4
    for (int k = 0; k < FF; k++) s += ip[k] * Wim[k * DD + d];
    d_Xall[b * DD + d] = s;
}

__global__ void k_gather(const int* __restrict__ tok, const float* __restrict__ embed) {
    int r = blockIdx.x;                              // s*32+b
    int s = r >> 5, b = r & 31;
    int t = tok[b * SS + s];
    const float4* src = (const float4*)(embed + (size_t)t * DD);
    float4* dst = (float4*)(d_Xall + (size_t)(BB + r) * DD);
    dst[threadIdx.x] = src[threadIdx.x];
}

__global__ void k_zero_pad() {
    int i = blockIdx.x * 256 + threadIdx.x;          // 49152
    d_Xall[NSTEPS * BB * DD + i] = 0.f;
}

__global__ void k_cb0p(const float* __restrict__ bw, const float* __restrict__ bu) {
    int n = blockIdx.x * 256 + threadIdx.x;          // 2048: n = j*4+g
    int g = n & 3, j = n >> 2;
    d_cb0p[n] = bw[g * HH + j] + bu[g * HH + j];
}

__global__ void k_cb1p(const float* __restrict__ bw, const float* __restrict__ bu,
                       const float* __restrict__ bxh, const float* __restrict__ Uh) {
    int n = blockIdx.x * 256 + threadIdx.x;          // 2048
    int g = n & 3, j = n >> 2;
    int col = g * HH + j;
    float s = bw[NG + col] + bu[NG + col];
    const float* U1 = Uh + (size_t)HH * NG;
    #pragma unroll 4
    for (int k = 0; k < DD; k++) s += bxh[k] * U1[(size_t)k * NG + col];
    d_cb1p[n] = s;
}

// Wp[k*2048 + j*4 + g] = W[k*2048 + g*512 + j]
__global__ void k_permW(const float* __restrict__ W, float* __restrict__ Wp) {
    int idx = blockIdx.x * 256 + threadIdx.x;        // 1048576
    int k = idx >> 11;
    int rest = idx & 2047;
    int j = rest >> 2, g = rest & 3;
    Wp[idx] = W[(size_t)k * NG + g * HH + j];
}

// transpose + hi/lo split of Wc: [512][32000] fp32 -> [32000][512] bf16 x2
__global__ void k_cvtWc(const float* __restrict__ Wc) {
    __shared__ float ts[32][33];
    int n0 = blockIdx.x * 32, k0 = blockIdx.y * 32;
    int tx = threadIdx.x & 31, ty = threadIdx.x >> 5;   // 32 x 8
    #pragma unroll
    for (int i = 0; i < 4; i++)
        ts[ty + i * 8][tx] = Wc[(size_t)(k0 + ty + i * 8) * VV + n0 + tx];
    __syncthreads();
    #pragma unroll
    for (int i = 0; i < 4; i++) {
        int n = n0 + ty + i * 8, k = k0 + tx;
        float v = ts[tx][ty + i * 8];
        __nv_bfloat16 h = __float2bfloat16(v);
        d_WcTh[(size_t)n * DD + k] = h;
        d_WcTl[(size_t)n * DD + k] = __float2bfloat16(v - __bfloat162float(h));
    }
}

// ---------------- fp32 SGEMM (precompute only) ----------------------------------
// remap 0: row-major C.  remap 2: Ux permute row r=(step*32+b) -> C[(step*N+col)*32+b].
// remap 3: write bf16 hi/lo split to Ch/Cl row-major.
__global__ __launch_bounds__(256) void k_sgemm(
    const float* __restrict__ A, const float* __restrict__ Bm, float* __restrict__ C,
    int N, int K, const float* __restrict__ bias, int remap,
    __nv_bfloat16* __restrict__ Ch, __nv_bfloat16* __restrict__ Cl)
{
    __shared__ __align__(16) float As[2][8][132];
    __shared__ __align__(16) float Bs[2][8][128];
    int tid = threadIdx.x;
    int bm = blockIdx.y * 128, bn = blockIdx.x * 128;
    int arow = tid >> 1, akq = (tid & 1) * 4;
    int brow = tid >> 5, bcol = (tid & 31) * 4;
    int tx = tid & 15, ty = tid >> 4;
    float acc[8][8];
    #pragma unroll
    for (int i = 0; i < 8; i++)
        #pragma unroll
        for (int j = 0; j < 8; j++) acc[i][j] = 0.f;

    const float* Ap = A + (size_t)(bm + arow) * K + akq;
    const float* Bp = Bm + (size_t)brow * N + bn + bcol;
    {
        float4 av = *(const float4*)Ap;
        float4 bv = *(const float4*)Bp;
        As[0][akq + 0][arow] = av.x; As[0][akq + 1][arow] = av.y;
        As[0][akq + 2][arow] = av.z; As[0][akq + 3][arow] = av.w;
        *(float4*)&Bs[0][brow][bcol] = bv;
    }
    __syncthreads();

    int ntiles = K >> 3;
    for (int t = 0; t < ntiles; t++) {
        int cur = t & 1;
        float4 av, bv;
        bool more = (t + 1 < ntiles);
        if (more) {
            av = *(const float4*)(Ap + (t + 1) * 8);
            bv = *(const float4*)(Bp + (size_t)(t + 1) * 8 * N);
        }
        #pragma unroll
        for (int kk = 0; kk < 8; kk++) {
            float a[8], b[8];
            *(float4*)(a)     = *(const float4*)&As[cur][kk][ty * 8];
            *(float4*)(a + 4) = *(const float4*)&As[cur][kk][ty * 8 + 4];
            *(float4*)(b)     = *(const float4*)&Bs[cur][kk][tx * 8];
            *(float4*)(b + 4) = *(const float4*)&Bs[cur][kk][tx * 8 + 4];
            #pragma unroll
            for (int i = 0; i < 8; i++)
                #pragma unroll
                for (int j = 0; j < 8; j++) acc[i][j] += a[i] * b[j];
        }
        if (more) {
            int nxt = cur ^ 1;
            As[nxt][akq + 0][arow] = av.x; As[nxt][akq + 1][arow] = av.y;
            As[nxt][akq + 2][arow] = av.z; As[nxt][akq + 3][arow] = av.w;
            *(float4*)&Bs[nxt][brow][bcol] = bv;
        }
        __syncthreads();
    }

    float bvals[8];
    #pragma unroll
    for (int j = 0; j < 8; j++) bvals[j] = bias ? bias[bn + tx * 8 + j] : 0.f;
    #pragma unroll
    for (int i = 0; i < 8; i++) {
        int r = bm + ty * 8 + i;
        if (remap == 2) {
            int st = r >> 5, bb = r & 31;
            #pragma unroll
            for (int jj = 0; jj < 8; jj++)
                C[((size_t)st * N + bn + tx * 8 + jj) * 32 + bb] = acc[i][jj] + bvals[jj];
        } else if (remap == 3) {
            #pragma unroll
            for (int jj = 0; jj < 8; jj++) {
                float v = acc[i][jj] + bvals[jj];
                __nv_bfloat16 h = __float2bfloat16(v);
                size_t o = (size_t)r * N + bn + tx * 8 + jj;
                Ch[o] = h;
                Cl[o] = __float2bfloat16(v - __bfloat162float(h));
            }
        } else {
            size_t rowoff = (size_t)r * N;
            float4 v0, v1;
            v0.x = acc[i][0] + bvals[0]; v0.y = acc[i][1] + bvals[1];
            v0.z = acc[i][2] + bvals[2]; v0.w = acc[i][3] + bvals[3];
            v1.x = acc[i][4] + bvals[4]; v1.y = acc[i][5] + bvals[5];
            v1.z = acc[i][6] + bvals[6]; v1.w = acc[i][7] + bvals[7];
            *(float4*)(C + rowoff + bn + tx * 8)     = v0;
            *(float4*)(C + rowoff + bn + tx * 8 + 4) = v1;
        }
    }
}

// ---------------- persistent recurrence kernel -----------------------------------
// 128 blocks x 256 threads, single wave. Weight slices cached in smem for all
// 129 steps. Cross-block state read with __ldcg (L1 not coherent intra-launch).

__device__ __forceinline__ void gsync() {
    __syncthreads();
    if (threadIdx.x == 0) {
        __threadfence();
        volatile unsigned* vg = &d_bar_gen;
        unsigned gen = *vg;
        if (atomicAdd(&d_bar_cnt, 1u) == RECUR_BLOCKS - 1) {
            d_bar_cnt = 0;
            __threadfence();
            atomicExch(&d_bar_gen, gen + 1);
        } else {
            while (*vg == gen) { }
            __threadfence();
        }
    }
    __syncthreads();
}

#define RECUR_SMEM ((3 * 8192 + 4096) * 4)   // ws0, ws1, wsm (8192 f) + red (4096 f)

__global__ __launch_bounds__(256) void k_recur() {
    extern __shared__ __align__(16) float sm[];
    float* ws0 = sm;                 // [512][16]
    float* ws1 = sm + 8192;
    float* wsm = sm + 16384;
    float* red = sm + 24576;         // [8][512]
    int tid = threadIdx.x;
    int b = tid & 31, kc = tid >> 5;
    int C0 = blockIdx.x * 16;

    // preload this block's weight slices (16 cols x 512 k each)
    for (int i = tid; i < 2048; i += 256) {          // i = k*4 + q (float4)
        int k = i >> 2, q = i & 3;
        ((float4*)ws0)[i] = *((const float4*)(d_Wp0 + (size_t)k * NG + C0) + q);
        ((float4*)ws1)[i] = *((const float4*)(d_Wp1 + (size_t)k * NG + C0) + q);
        ((float4*)wsm)[i] = *((const float4*)(d_Mp  + (size_t)k * NG + C0) + q);
    }
    __syncthreads();

    for (int t = 0; t < NSTEPS; t++) {
        int ping = t & 1;

        // ---------- cell 0 ----------
        {
            const float* hT = d_h0T[ping];
            float acc[16];
            #pragma unroll
            for (int c = 0; c < 16; c++) acc[c] = 0.f;
            int k0 = kc * 64;
            #pragma unroll 8
            for (int k = k0; k < k0 + 64; k++) {
                float hv = __ldcg(hT + k * BB + b);
                const float4* w = (const float4*)(ws0 + k * 16);
                float4 w0 = w[0], w1 = w[1], w2 = w[2], w3 = w[3];
                acc[0]  += hv * w0.x; acc[1]  += hv * w0.y; acc[2]  += hv * w0.z; acc[3]  += hv * w0.w;
                acc[4]  += hv * w1.x; acc[5]  += hv * w1.y; acc[6]  += hv * w1.z; acc[7]  += hv * w1.w;
                acc[8]  += hv * w2.x; acc[9]  += hv * w2.y; acc[10] += hv * w2.z; acc[11] += hv * w2.w;
                acc[12] += hv * w3.x; acc[13] += hv * w3.y; acc[14] += hv * w3.z; acc[15] += hv * w3.w;
            }
            #pragma unroll
            for (int c = 0; c < 16; c++) red[kc * 512 + c * 32 + b] = acc[c];
            __syncthreads();
            #pragma unroll
            for (int s = tid; s < 512; s += 256) {
                int c = s >> 5, bb = s & 31;
                float v = d_Uxp[((size_t)t * NG + C0 + c) * 32 + bb];
                #pragma unroll
                for (int q = 0; q < 8; q++) v += red[q * 512 + s];
                red[s] = v;
            }
            __syncthreads();
            if (tid < 128) {
                int bb = tid & 31, jl = tid >> 5;
                float gf = red[(jl * 4 + 0) * 32 + bb];
                float gi = red[(jl * 4 + 1) * 32 + bb];
                float go = red[(jl * 4 + 2) * 32 + bb];
                float gc = red[(jl * 4 + 3) * 32 + bb];
                float f  = 1.f / (1.f + expf(-gf));
                float ii = 1.f / (1.f + expf(-gi));
                float o  = 1.f / (1.f + expf(-go));
                int jg = blockIdx.x * 4 + jl;
                float c  = d_c0T[jg * 32 + bb];
                float cn = f * c + ii * tanhf(gc);
                d_c0T[jg * 32 + bb] = cn;
                d_h0T[ping ^ 1][jg * 32 + bb] = o * tanhf(cn);
            }
        }
        gsync();

        // ---------- cell 1 ----------
        {
            const float* h1 = d_h1T[ping];
            const float* h0 = d_h0T[ping ^ 1];
            float acc[16];
            #pragma unroll
            for (int c = 0; c < 16; c++) acc[c] = 0.f;
            int k0 = kc * 64;
            #pragma unroll 4
            for (int k = k0; k < k0 + 64; k++) {
                float hv = __ldcg(h1 + k * BB + b);
                float xv = __ldcg(h0 + k * BB + b);
                const float4* w = (const float4*)(ws1 + k * 16);
                const float4* m = (const float4*)(wsm + k * 16);
                #pragma unroll
                for (int q = 0; q < 4; q++) {
                    float4 wv = w[q], mv = m[q];
                    acc[q * 4 + 0] += hv * wv.x + xv * mv.x;
                    acc[q * 4 + 1] += hv * wv.y + xv * mv.y;
                    acc[q * 4 + 2] += hv * wv.z + xv * mv.z;
                    acc[q * 4 + 3] += hv * wv.w + xv * mv.w;
                }
            }
            #pragma unroll
            for (int c = 0; c < 16; c++) red[kc * 512 + c * 32 + b] = acc[c];
            __syncthreads();
            #pragma unroll
            for (int s = tid; s < 512; s += 256) {
                int c = s >> 5;
                float v = d_cb1p[C0 + c];
                #pragma unroll
                for (int q = 0; q < 8; q++) v += red[q * 512 + s];
                red[s] = v;
            }
            __syncthreads();
            if (tid < 128) {
                int bb = tid & 31, jl = tid >> 5;
                float gf = red[(jl * 4 + 0) * 32 + bb];
                float gi = red[(jl * 4 + 1) * 32 + bb];
                float go = red[(jl * 4 + 2) * 32 + bb];
                float gc = red[(jl * 4 + 3) * 32 + bb];
                float f  = 1.f / (1.f + expf(-gf));
                float ii = 1.f / (1.f + expf(-gi));
                float o  = 1.f / (1.f + expf(-go));
                int jg = blockIdx.x * 4 + jl;
                float c  = d_c1T[jg * 32 + bb];
                float cn = f * c + ii * tanhf(gc);
                d_c1T[jg * 32 + bb] = cn;
                float hn = o * tanhf(cn);
                d_h1T[ping ^ 1][jg * 32 + bb] = hn;
                if (t >= 1)
                    d_Hs[((size_t)bb * SS + (t - 1)) * HH + jg] = hn;
            }
        }
        gsync();
    }
}

// ---------------- HMMA classifier: out = P @ WcT^T + bc --------------------------

__device__ __forceinline__ uint32_t smem_u32(const void* p) {
    uint32_t a;
    asm("{ .reg .u64 t; cvta.to.shared.u64 t, %1; cvt.u32.u64 %0, t; }" : "=r"(a) : "l"(p));
    return a;
}

#define LDSM4(R0, R1, R2, R3, ADDR) \
    asm volatile("ldmatrix.sync.aligned.m8n8.x4.shared.b16 {%0,%1,%2,%3}, [%4];" \
                 : "=r"(R0), "=r"(R1), "=r"(R2), "=r"(R3) : "r"(ADDR))

#define MMA16816(C, A, B0, B1) \
    asm volatile("mma.sync.aligned.m16n8k16.row.col.f32.bf16.bf16.f32 " \
                 "{%0,%1,%2,%3}, {%4,%5,%6,%7}, {%8,%9}, {%0,%1,%2,%3};" \
                 : "+f"((C)[0]), "+f"((C)[1]), "+f"((C)[2]), "+f"((C)[3]) \
                 : "r"((A)[0]), "r"((A)[1]), "r"((A)[2]), "r"((A)[3]), "r"(B0), "r"(B1))

__global__ __launch_bounds__(256) void k_clf(const float* __restrict__ bias,
                                             float* __restrict__ out) {
    __shared__ __align__(16) __nv_bfloat16 sAh[128 * 40];
    __shared__ __align__(16) __nv_bfloat16 sAl[128 * 40];
    __shared__ __align__(16) __nv_bfloat16 sBh[128 * 40];
    __shared__ __align__(16) __nv_bfloat16 sBl[128 * 40];
    int tid = threadIdx.x;
    int lane = tid & 31, warp = tid >> 5;
    int n0 = blockIdx.x * 128, m0 = blockIdx.y * 128;
    int wm = (warp >> 1) * 32;
    int wn = (warp & 1) * 64;

    float acc[2][8][4];
    #pragma unroll
    for (int i = 0; i < 2; i++)
        #pragma unroll
        for (int j = 0; j < 8; j++)
            #pragma unroll
            for (int q = 0; q < 4; q++) acc[i][j][q] = 0.f;

    int lrow = tid >> 1;
    int lq0 = (tid & 1) * 2;
    const uint4* gAh = (const uint4*)d_Ph   + (size_t)(m0 + lrow) * 64 + lq0;
    const uint4* gAl = (const uint4*)d_Pl   + (size_t)(m0 + lrow) * 64 + lq0;
    const uint4* gBh = (const uint4*)d_WcTh + (size_t)(n0 + lrow) * 64 + lq0;
    const uint4* gBl = (const uint4*)d_WcTl + (size_t)(n0 + lrow) * 64 + lq0;

    int r16 = lane & 15;
    uint32_t lmoff = (uint32_t)(r16 * 80 + (lane >> 4) * 16);
    uint32_t aAh = smem_u32(sAh) + lmoff, aAl = smem_u32(sAl) + lmoff;
    uint32_t aBh = smem_u32(sBh) + lmoff, aBl = smem_u32(sBl) + lmoff;

    for (int kc = 0; kc < 16; kc++) {
        if (kc) __syncthreads();
        #pragma unroll
        for (int i = 0; i < 2; i++) {
            *(uint4*)(sAh + lrow * 40 + (lq0 + i) * 8) = gAh[kc * 4 + i];
            *(uint4*)(sAl + lrow * 40 + (lq0 + i) * 8) = gAl[kc * 4 + i];
            *(uint4*)(sBh + lrow * 40 + (lq0 + i) * 8) = gBh[kc * 4 + i];
            *(uint4*)(sBl + lrow * 40 + (lq0 + i) * 8) = gBl[kc * 4 + i];
        }
        __syncthreads();
        #pragma unroll
        for (int k16 = 0; k16 < 2; k16++) {
            uint32_t kb = k16 * 32;
            uint32_t ah[2][4], al[2][4];
            #pragma unroll
            for (int mf = 0; mf < 2; mf++) {
                uint32_t off = (uint32_t)((wm + mf * 16) * 80) + kb;
                LDSM4(ah[mf][0], ah[mf][1], ah[mf][2], ah[mf][3], aAh + off);
                LDSM4(al[mf][0], al[mf][1], al[mf][2], al[mf][3], aAl + off);
            }
            #pragma unroll
            for (int g = 0; g < 4; g++) {
                uint32_t off = (uint32_t)((wn + g * 16) * 80) + kb;
                uint32_t bh0, bh1, bh2, bh3, bl0, bl1, bl2, bl3;
                LDSM4(bh0, bh1, bh2, bh3, aBh + off);
                LDSM4(bl0, bl1, bl2, bl3, aBl + off);
                #pragma unroll
                for (int mf = 0; mf < 2; mf++) {
                    MMA16816(acc[mf][g * 2],     ah[mf], bh0, bh2);
                    MMA16816(acc[mf][g * 2 + 1], ah[mf], bh1, bh3);
                    MMA16816(acc[mf][g * 2],     ah[mf], bl0, bl2);
                    MMA16816(acc[mf][g * 2 + 1], ah[mf], bl1, bl3);
                    MMA16816(acc[mf][g * 2],     al[mf], bh0, bh2);
                    MMA16816(acc[mf][g * 2 + 1], al[mf], bh1, bh3);
                }
            }
        }
    }

    #pragma unroll
    for (int mf = 0; mf < 2; mf++) {
        int m = m0 + wm + mf * 16 + (lane >> 2);
        float* o0 = out + (size_t)m * VV;
        float* o1 = out + (size_t)(m + 8) * VV;
        #pragma unroll
        for (int nf = 0; nf < 8; nf++) {
            int n = n0 + wn + nf * 8 + (lane & 3) * 2;
            float b0v = bias[n], b1v = bias[n + 1];
            float2 v0, v1;
            v0.x = acc[mf][nf][0] + b0v; v0.y = acc[mf][nf][1] + b1v;
            v1.x = acc[mf][nf][2] + b0v; v1.y = acc[mf][nf][3] + b1v;
            *(float2*)(o0 + n) = v0;
            *(float2*)(o1 + n) = v1;
        }
    }
}

// ---------------- launch --------------------------------------------------------

extern "C" void kernel_launch(void* const* d_in, const int* in_sizes, int n_in,
                              void* d_out, int out_size) {
    const float* im    = (const float*)d_in[0];
    const int*   tok   = (const int*)  d_in[1];
    const float* h0    = (const float*)d_in[2];
    const float* c0    = (const float*)d_in[3];
    const float* embed = (const float*)d_in[4];
    const float* W_im  = (const float*)d_in[5];
    const float* b_im  = (const float*)d_in[6];
    const float* Wh    = (const float*)d_in[7];
    const float* bw    = (const float*)d_in[8];
    const float* Uh    = (const float*)d_in[9];
    const float* bu    = (const float*)d_in[10];
    const float* Wxh   = (const float*)d_in[11];
    const float* bxh   = (const float*)d_in[12];
    const float* Wc    = (const float*)d_in[13];
    const float* bc    = (const float*)d_in[14];
    float* out = (float*)d_out;

    float *pXall, *pUxp, *pM, *pMp, *pUp0, *pWp0, *pWp1, *pcb0p, *pHs;
    __nv_bfloat16 *pPh, *pPl;
    cudaGetSymbolAddress((void**)&pXall, d_Xall);
    cudaGetSymbolAddress((void**)&pUxp,  d_Uxp);
    cudaGetSymbolAddress((void**)&pM,    d_M);
    cudaGetSymbolAddress((void**)&pMp,   d_Mp);
    cudaGetSymbolAddress((void**)&pUp0,  d_Up0);
    cudaGetSymbolAddress((void**)&pWp0,  d_Wp0);
    cudaGetSymbolAddress((void**)&pWp1,  d_Wp1);
    cudaGetSymbolAddress((void**)&pcb0p, d_cb0p);
    cudaGetSymbolAddress((void**)&pHs,   d_Hs);
    cudaGetSymbolAddress((void**)&pPh,   d_Ph);
    cudaGetSymbolAddress((void**)&pPl,   d_Pl);

    cudaFuncSetAttribute(k_recur, cudaFuncAttributeMaxDynamicSharedMemorySize, RECUR_SMEM);

    // ---- setup (off critical path) ----
    k_init    <<<64, 256>>>(h0, c0);
    k_ximg    <<<64, 256>>>(im, W_im, b_im);
    k_gather  <<<4096, 128>>>(tok, embed);
    k_zero_pad<<<192, 256>>>();
    k_cb0p    <<<8, 256>>>(bw, bu);
    k_cb1p    <<<8, 256>>>(bw, bu, bxh, Uh);
    k_permW   <<<4096, 256>>>(Wh, pWp0);
    k_permW   <<<4096, 256>>>(Wh + (size_t)HH * NG, pWp1);
    k_permW   <<<4096, 256>>>(Uh, pUp0);
    k_cvtWc   <<<dim3(1000, 16), 256>>>(Wc);

    // M = Wxh0 @ Uh1, then permute
    k_sgemm<<<dim3(16, 4), 256>>>(Wxh, Uh + (size_t)HH * NG, pM, NG, DD, nullptr, 0,
                                  nullptr, nullptr);
    k_permW<<<4096, 256>>>(pM, pMp);

    // Uxp = Xall @ Up0 + cb0p, permuted-write [step][col][b]
    k_sgemm<<<dim3(16, 33), 256>>>(pXall, pUp0, pUxp, NG, DD, pcb0p, 2,
                                   nullptr, nullptr);

    // ---- whole recurrence: single persistent kernel ----
    k_recur<<<RECUR_BLOCKS, 256, RECUR_SMEM>>>();

    // P = Hs @ Wxh1 + bxh1, split bf16 hi/lo
    k_sgemm<<<dim3(4, 32), 256>>>(pHs, Wxh + (size_t)HH * DD, nullptr, DD, DD,
                                  bxh + DD, 3, pPh, pPl);

    // logits = P @ Wc + bc on tensor cores (split precision)
    k_clf<<<dim3(250, 32), 256>>>(bc, out);
}

// round 14
// speedup vs baseline: 3.8763x; 1.1586x over previous
#include <cuda_runtime.h>
#include <cuda_bf16.h>
#include <math.h>
#include <stdint.h>
#include <stddef.h>

#define BB 32
#define SS 128
#define HH 512
#define DD 512
#define VV 32000
#define FF 768
#define NG 2048          // 4*H
#define NSTEPS 129
#define ROWS_PAD 4224    // 132*32
#define RECUR_BLOCKS 128

// ---------------- static device scratch ----------------------------------------
__device__ __align__(16) float d_Xall[ROWS_PAD * DD];
__device__ __align__(16) __nv_bfloat16 d_Xh[ROWS_PAD * DD];   // Xall hi
__device__ __align__(16) __nv_bfloat16 d_Xl[ROWS_PAD * DD];   // Xall lo
__device__ __align__(16) __nv_bfloat16 d_U0Th[NG * DD];       // Uh0^T permuted hi [colp][k]
__device__ __align__(16) __nv_bfloat16 d_U0Tl[NG * DD];
__device__ __align__(16) float d_Uxp [ROWS_PAD * NG];     // [step][col][b]
__device__ __align__(16) float d_M   [DD * NG];
__device__ __align__(16) float d_Mp  [DD * NG];
__device__ __align__(16) float d_Wp0 [HH * NG];
__device__ __align__(16) float d_Wp1 [HH * NG];
__device__ __align__(16) __nv_bfloat16 d_WcTh[VV * DD];   // Wc^T hi  [n][k]
__device__ __align__(16) __nv_bfloat16 d_WcTl[VV * DD];   // Wc^T lo
__device__ __align__(16) float d_Hs[BB * SS * HH];        // layer-1 h, row b*128+s
__device__ __align__(16) __nv_bfloat16 d_Ph[BB * SS * DD];// P hi [b*128+s][k]
__device__ __align__(16) __nv_bfloat16 d_Pl[BB * SS * DD];// P lo
__device__ __align__(16) float d_cb0p[NG];
__device__ __align__(16) float d_cb1p[NG];
__device__ __align__(16) float d_h0T [2][HH * BB];        // transposed [j][b]
__device__ __align__(16) float d_h1T [2][HH * BB];
__device__ __align__(16) float d_c0T [HH * BB];
__device__ __align__(16) float d_c1T [HH * BB];
__device__ unsigned d_bar_cnt;
__device__ unsigned d_bar_gen;

// ---------------- setup kernels -------------------------------------------------

__global__ void k_init(const float* __restrict__ h0, const float* __restrict__ c0) {
    int i = blockIdx.x * 256 + threadIdx.x;          // 16384
    int b = i & 31, j = i >> 5;
    d_h0T[0][j * BB + b] = h0[b * HH + j];
    d_h1T[0][j * BB + b] = h0[BB * HH + b * HH + j];
    d_c0T[j * BB + b]    = c0[b * HH + j];
    d_c1T[j * BB + b]    = c0[BB * HH + b * HH + j];
}

__global__ void k_ximg(const float* __restrict__ im, const float* __restrict__ Wim,
                       const float* __restrict__ bim) {
    int idx = blockIdx.x * 256 + threadIdx.x;        // 16384
    int b = idx >> 9, d = idx & 511;
    float s = bim[d];
    const float* ip = im + b * FF;
    #pragma unroll 4
    for (int k = 0; k < FF; k++) s += ip[k] * Wim[k * DD + d];
    d_Xall[b * DD + d] = s;
}

__global__ void k_gather(const int* __restrict__ tok, const float* __restrict__ embed) {
    int r = blockIdx.x;                              // s*32+b
    int s = r >> 5, b = r & 31;
    int t = tok[b * SS + s];
    const float4* src = (const float4*)(embed + (size_t)t * DD);
    float4* dst = (float4*)(d_Xall + (size_t)(BB + r) * DD);
    dst[threadIdx.x] = src[threadIdx.x];
}

__global__ void k_zero_pad() {
    int i = blockIdx.x * 256 + threadIdx.x;          // 49152
    d_Xall[NSTEPS * BB * DD + i] = 0.f;
}

// Xall -> split bf16 (rows 0..4223)
__global__ void k_cvtX() {
    int i = blockIdx.x * 256 + threadIdx.x;          // 2162688 = 8448*256
    float v = d_Xall[i];
    __nv_bfloat16 h = __float2bfloat16(v);
    d_Xh[i] = h;
    d_Xl[i] = __float2bfloat16(v - __bfloat162float(h));
}

// Uh0 -> transposed+permuted split bf16: U0T[j*4+g][k] = Uh0[k][g*512+j]
__global__ void k_cvtU0T(const float* __restrict__ Uh) {
    int idx = blockIdx.x * 256 + threadIdx.x;        // 1048576 = 4096*256
    int colp = idx >> 9, k = idx & 511;
    int j = colp >> 2, g = colp & 3;
    float v = Uh[(size_t)k * NG + g * HH + j];
    __nv_bfloat16 h = __float2bfloat16(v);
    d_U0Th[idx] = h;
    d_U0Tl[idx] = __float2bfloat16(v - __bfloat162float(h));
}

__global__ void k_cb0p(const float* __restrict__ bw, const float* __restrict__ bu) {
    int n = blockIdx.x * 256 + threadIdx.x;          // 2048: n = j*4+g
    int g = n & 3, j = n >> 2;
    d_cb0p[n] = bw[g * HH + j] + bu[g * HH + j];
}

__global__ void k_cb1p(const float* __restrict__ bw, const float* __restrict__ bu,
                       const float* __restrict__ bxh, const float* __restrict__ Uh) {
    int n = blockIdx.x * 256 + threadIdx.x;          // 2048
    int g = n & 3, j = n >> 2;
    int col = g * HH + j;
    float s = bw[NG + col] + bu[NG + col];
    const float* U1 = Uh + (size_t)HH * NG;
    #pragma unroll 4
    for (int k = 0; k < DD; k++) s += bxh[k] * U1[(size_t)k * NG + col];
    d_cb1p[n] = s;
}

// Wp[k*2048 + j*4 + g] = W[k*2048 + g*512 + j]
__global__ void k_permW(const float* __restrict__ W, float* __restrict__ Wp) {
    int idx = blockIdx.x * 256 + threadIdx.x;        // 1048576
    int k = idx >> 11;
    int rest = idx & 2047;
    int j = rest >> 2, g = rest & 3;
    Wp[idx] = W[(size_t)k * NG + g * HH + j];
}

// transpose + hi/lo split of Wc: [512][32000] fp32 -> [32000][512] bf16 x2
__global__ void k_cvtWc(const float* __restrict__ Wc) {
    __shared__ float ts[32][33];
    int n0 = blockIdx.x * 32, k0 = blockIdx.y * 32;
    int tx = threadIdx.x & 31, ty = threadIdx.x >> 5;   // 32 x 8
    #pragma unroll
    for (int i = 0; i < 4; i++)
        ts[ty + i * 8][tx] = Wc[(size_t)(k0 + ty + i * 8) * VV + n0 + tx];
    __syncthreads();
    #pragma unroll
    for (int i = 0; i < 4; i++) {
        int n = n0 + ty + i * 8, k = k0 + tx;
        float v = ts[tx][ty + i * 8];
        __nv_bfloat16 h = __float2bfloat16(v);
        d_WcTh[(size_t)n * DD + k] = h;
        d_WcTl[(size_t)n * DD + k] = __float2bfloat16(v - __bfloat162float(h));
    }
}

// ---------------- fp32 SGEMM (precompute only) ----------------------------------
// remap 0: row-major C.  remap 3: write bf16 hi/lo split to Ch/Cl row-major.
__global__ __launch_bounds__(256) void k_sgemm(
    const float* __restrict__ A, const float* __restrict__ Bm, float* __restrict__ C,
    int N, int K, const float* __restrict__ bias, int remap,
    __nv_bfloat16* __restrict__ Ch, __nv_bfloat16* __restrict__ Cl)
{
    __shared__ __align__(16) float As[2][8][132];
    __shared__ __align__(16) float Bs[2][8][128];
    int tid = threadIdx.x;
    int bm = blockIdx.y * 128, bn = blockIdx.x * 128;
    int arow = tid >> 1, akq = (tid & 1) * 4;
    int brow = tid >> 5, bcol = (tid & 31) * 4;
    int tx = tid & 15, ty = tid >> 4;
    float acc[8][8];
    #pragma unroll
    for (int i = 0; i < 8; i++)
        #pragma unroll
        for (int j = 0; j < 8; j++) acc[i][j] = 0.f;

    const float* Ap = A + (size_t)(bm + arow) * K + akq;
    const float* Bp = Bm + (size_t)brow * N + bn + bcol;
    {
        float4 av = *(const float4*)Ap;
        float4 bv = *(const float4*)Bp;
        As[0][akq + 0][arow] = av.x; As[0][akq + 1][arow] = av.y;
        As[0][akq + 2][arow] = av.z; As[0][akq + 3][arow] = av.w;
        *(float4*)&Bs[0][brow][bcol] = bv;
    }
    __syncthreads();

    int ntiles = K >> 3;
    for (int t = 0; t < ntiles; t++) {
        int cur = t & 1;
        float4 av, bv;
        bool more = (t + 1 < ntiles);
        if (more) {
            av = *(const float4*)(Ap + (t + 1) * 8);
            bv = *(const float4*)(Bp + (size_t)(t + 1) * 8 * N);
        }
        #pragma unroll
        for (int kk = 0; kk < 8; kk++) {
            float a[8], b[8];
            *(float4*)(a)     = *(const float4*)&As[cur][kk][ty * 8];
            *(float4*)(a + 4) = *(const float4*)&As[cur][kk][ty * 8 + 4];
            *(float4*)(b)     = *(const float4*)&Bs[cur][kk][tx * 8];
            *(float4*)(b + 4) = *(const float4*)&Bs[cur][kk][tx * 8 + 4];
            #pragma unroll
            for (int i = 0; i < 8; i++)
                #pragma unroll
                for (int j = 0; j < 8; j++) acc[i][j] += a[i] * b[j];
        }
        if (more) {
            int nxt = cur ^ 1;
            As[nxt][akq + 0][arow] = av.x; As[nxt][akq + 1][arow] = av.y;
            As[nxt][akq + 2][arow] = av.z; As[nxt][akq + 3][arow] = av.w;
            *(float4*)&Bs[nxt][brow][bcol] = bv;
        }
        __syncthreads();
    }

    float bvals[8];
    #pragma unroll
    for (int j = 0; j < 8; j++) bvals[j] = bias ? bias[bn + tx * 8 + j] : 0.f;
    #pragma unroll
    for (int i = 0; i < 8; i++) {
        int r = bm + ty * 8 + i;
        if (remap == 3) {
            #pragma unroll
            for (int jj = 0; jj < 8; jj++) {
                float v = acc[i][jj] + bvals[jj];
                __nv_bfloat16 h = __float2bfloat16(v);
                size_t o = (size_t)r * N + bn + tx * 8 + jj;
                Ch[o] = h;
                Cl[o] = __float2bfloat16(v - __bfloat162float(h));
            }
        } else {
            size_t rowoff = (size_t)r * N;
            float4 v0, v1;
            v0.x = acc[i][0] + bvals[0]; v0.y = acc[i][1] + bvals[1];
            v0.z = acc[i][2] + bvals[2]; v0.w = acc[i][3] + bvals[3];
            v1.x = acc[i][4] + bvals[4]; v1.y = acc[i][5] + bvals[5];
            v1.z = acc[i][6] + bvals[6]; v1.w = acc[i][7] + bvals[7];
            *(float4*)(C + rowoff + bn + tx * 8)     = v0;
            *(float4*)(C + rowoff + bn + tx * 8 + 4) = v1;
        }
    }
}

// ---------------- persistent recurrence kernel -----------------------------------

__device__ __forceinline__ void gsync() {
    __syncthreads();
    if (threadIdx.x == 0) {
        __threadfence();
        volatile unsigned* vg = &d_bar_gen;
        unsigned gen = *vg;
        if (atomicAdd(&d_bar_cnt, 1u) == RECUR_BLOCKS - 1) {
            d_bar_cnt = 0;
            __threadfence();
            atomicExch(&d_bar_gen, gen + 1);
        } else {
            while (*vg == gen) { }
            __threadfence();
        }
    }
    __syncthreads();
}

#define RECUR_SMEM ((3 * 8192 + 4096) * 4)

__global__ __launch_bounds__(256) void k_recur() {
    extern __shared__ __align__(16) float sm[];
    float* ws0 = sm;                 // [512][16]
    float* ws1 = sm + 8192;
    float* wsm = sm + 16384;
    float* red = sm + 24576;         // [8][512]
    int tid = threadIdx.x;
    int b = tid & 31, kc = tid >> 5;
    int C0 = blockIdx.x * 16;

    for (int i = tid; i < 2048; i += 256) {          // i = k*4 + q (float4)
        int k = i >> 2, q = i & 3;
        ((float4*)ws0)[i] = *((const float4*)(d_Wp0 + (size_t)k * NG + C0) + q);
        ((float4*)ws1)[i] = *((const float4*)(d_Wp1 + (size_t)k * NG + C0) + q);
        ((float4*)wsm)[i] = *((const float4*)(d_Mp  + (size_t)k * NG + C0) + q);
    }
    __syncthreads();

    for (int t = 0; t < NSTEPS; t++) {
        int ping = t & 1;

        // ---------- cell 0 ----------
        {
            const float* hT = d_h0T[ping];
            float acc[16];
            #pragma unroll
            for (int c = 0; c < 16; c++) acc[c] = 0.f;
            int k0 = kc * 64;
            #pragma unroll 8
            for (int k = k0; k < k0 + 64; k++) {
                float hv = __ldcg(hT + k * BB + b);
                const float4* w = (const float4*)(ws0 + k * 16);
                float4 w0 = w[0], w1 = w[1], w2 = w[2], w3 = w[3];
                acc[0]  += hv * w0.x; acc[1]  += hv * w0.y; acc[2]  += hv * w0.z; acc[3]  += hv * w0.w;
                acc[4]  += hv * w1.x; acc[5]  += hv * w1.y; acc[6]  += hv * w1.z; acc[7]  += hv * w1.w;
                acc[8]  += hv * w2.x; acc[9]  += hv * w2.y; acc[10] += hv * w2.z; acc[11] += hv * w2.w;
                acc[12] += hv * w3.x; acc[13] += hv * w3.y; acc[14] += hv * w3.z; acc[15] += hv * w3.w;
            }
            #pragma unroll
            for (int c = 0; c < 16; c++) red[kc * 512 + c * 32 + b] = acc[c];
            __syncthreads();
            #pragma unroll
            for (int s = tid; s < 512; s += 256) {
                int c = s >> 5, bb = s & 31;
                float v = d_Uxp[((size_t)t * NG + C0 + c) * 32 + bb];
                #pragma unroll
                for (int q = 0; q < 8; q++) v += red[q * 512 + s];
                red[s] = v;
            }
            __syncthreads();
            if (tid < 128) {
                int bb = tid & 31, jl = tid >> 5;
                float gf = red[(jl * 4 + 0) * 32 + bb];
                float gi = red[(jl * 4 + 1) * 32 + bb];
                float go = red[(jl * 4 + 2) * 32 + bb];
                float gc = red[(jl * 4 + 3) * 32 + bb];
                float f  = 1.f / (1.f + expf(-gf));
                float ii = 1.f / (1.f + expf(-gi));
                float o  = 1.f / (1.f + expf(-go));
                int jg = blockIdx.x * 4 + jl;
                float c  = d_c0T[jg * 32 + bb];
                float cn = f * c + ii * tanhf(gc);
                d_c0T[jg * 32 + bb] = cn;
                d_h0T[ping ^ 1][jg * 32 + bb] = o * tanhf(cn);
            }
        }
        gsync();

        // ---------- cell 1 ----------
        {
            const float* h1 = d_h1T[ping];
            const float* h0 = d_h0T[ping ^ 1];
            float acc[16];
            #pragma unroll
            for (int c = 0; c < 16; c++) acc[c] = 0.f;
            int k0 = kc * 64;
            #pragma unroll 4
            for (int k = k0; k < k0 + 64; k++) {
                float hv = __ldcg(h1 + k * BB + b);
                float xv = __ldcg(h0 + k * BB + b);
                const float4* w = (const float4*)(ws1 + k * 16);
                const float4* m = (const float4*)(wsm + k * 16);
                #pragma unroll
                for (int q = 0; q < 4; q++) {
                    float4 wv = w[q], mv = m[q];
                    acc[q * 4 + 0] += hv * wv.x + xv * mv.x;
                    acc[q * 4 + 1] += hv * wv.y + xv * mv.y;
                    acc[q * 4 + 2] += hv * wv.z + xv * mv.z;
                    acc[q * 4 + 3] += hv * wv.w + xv * mv.w;
                }
            }
            #pragma unroll
            for (int c = 0; c < 16; c++) red[kc * 512 + c * 32 + b] = acc[c];
            __syncthreads();
            #pragma unroll
            for (int s = tid; s < 512; s += 256) {
                int c = s >> 5;
                float v = d_cb1p[C0 + c];
                #pragma unroll
                for (int q = 0; q < 8; q++) v += red[q * 512 + s];
                red[s] = v;
            }
            __syncthreads();
            if (tid < 128) {
                int bb = tid & 31, jl = tid >> 5;
                float gf = red[(jl * 4 + 0) * 32 + bb];
                float gi = red[(jl * 4 + 1) * 32 + bb];
                float go = red[(jl * 4 + 2) * 32 + bb];
                float gc = red[(jl * 4 + 3) * 32 + bb];
                float f  = 1.f / (1.f + expf(-gf));
                float ii = 1.f / (1.f + expf(-gi));
                float o  = 1.f / (1.f + expf(-go));
                int jg = blockIdx.x * 4 + jl;
                float c  = d_c1T[jg * 32 + bb];
                float cn = f * c + ii * tanhf(gc);
                d_c1T[jg * 32 + bb] = cn;
                float hn = o * tanhf(cn);
                d_h1T[ping ^ 1][jg * 32 + bb] = hn;
                if (t >= 1)
                    d_Hs[((size_t)bb * SS + (t - 1)) * HH + jg] = hn;
            }
        }
        gsync();
    }
}

// ---------------- split-bf16 HMMA GEMM core (cp.async 2-stage pipeline) ----------
// smem stage layout (bytes): Ah 0, Al 10240, Bh 20480, Bl 30720; stage stride 40960.

__device__ __forceinline__ uint32_t smem_u32(const void* p) {
    uint32_t a;
    asm("{ .reg .u64 t; cvta.to.shared.u64 t, %1; cvt.u32.u64 %0, t; }" : "=r"(a) : "l"(p));
    return a;
}
__device__ __forceinline__ void cpa16(uint32_t dst, const void* src) {
    asm volatile("cp.async.cg.shared.global [%0], [%1], 16;" :: "r"(dst), "l"(src));
}

#define LDSM4(R0, R1, R2, R3, ADDR) \
    asm volatile("ldmatrix.sync.aligned.m8n8.x4.shared.b16 {%0,%1,%2,%3}, [%4];" \
                 : "=r"(R0), "=r"(R1), "=r"(R2), "=r"(R3) : "r"(ADDR))

#define MMA16816(C, A, B0, B1) \
    asm volatile("mma.sync.aligned.m16n8k16.row.col.f32.bf16.bf16.f32 " \
                 "{%0,%1,%2,%3}, {%4,%5,%6,%7}, {%8,%9}, {%0,%1,%2,%3};" \
                 : "+f"((C)[0]), "+f"((C)[1]), "+f"((C)[2]), "+f"((C)[3]) \
                 : "r"((A)[0]), "r"((A)[1]), "r"((A)[2]), "r"((A)[3]), "r"(B0), "r"(B1))

#define HMMA_SMEM 81920

// Shared body: computes acc for tile (m0, n0) over K=512 with pipeline.
#define HMMA_BODY(AHP, ALP, BHP, BLP)                                              \
    extern __shared__ __align__(16) char smraw[];                                  \
    uint32_t smb = smem_u32(smraw);                                                \
    int tid = threadIdx.x;                                                         \
    int lane = tid & 31, warp = tid >> 5;                                          \
    int wm = (warp >> 1) * 32;                                                     \
    int wn = (warp & 1) * 64;                                                      \
    float acc[2][8][4];                                                            \
    _Pragma("unroll")                                                              \
    for (int i = 0; i < 2; i++)                                                    \
        _Pragma("unroll")                                                          \
        for (int j = 0; j < 8; j++)                                                \
            _Pragma("unroll")                                                      \
            for (int q = 0; q < 4; q++) acc[i][j][q] = 0.f;                        \
    int lrow = tid >> 1;                                                           \
    int lq0 = (tid & 1) * 2;                                                       \
    const uint4* gAh = (const uint4*)(AHP) + (size_t)(m0 + lrow) * 64 + lq0;       \
    const uint4* gAl = (const uint4*)(ALP) + (size_t)(m0 + lrow) * 64 + lq0;       \
    const uint4* gBh = (const uint4*)(BHP) + (size_t)(n0 + lrow) * 64 + lq0;       \
    const uint4* gBl = (const uint4*)(BLP) + (size_t)(n0 + lrow) * 64 + lq0;       \
    uint32_t roff0 = (uint32_t)(lrow * 40 + lq0 * 8) * 2;                          \
    int r16 = lane & 15;                                                           \
    uint32_t lmoff = (uint32_t)(r16 * 80 + (lane >> 4) * 16);                      \
    { uint32_t db = smb;                                                           \
      _Pragma("unroll")                                                            \
      for (int i = 0; i < 2; i++) {                                                \
          uint32_t ro = roff0 + i * 16;                                            \
          cpa16(db + ro,          gAh + i);                                        \
          cpa16(db + 10240u + ro, gAl + i);                                        \
          cpa16(db + 20480u + ro, gBh + i);                                        \
          cpa16(db + 30720u + ro, gBl + i);                                        \
      }                                                                            \
      asm volatile("cp.async.commit_group;" ::: "memory"); }                       \
    for (int kc = 0; kc < 16; kc++) {                                              \
        if (kc < 15) {                                                             \
            uint32_t db = smb + (uint32_t)((kc + 1) & 1) * 40960u;                 \
            _Pragma("unroll")                                                      \
            for (int i = 0; i < 2; i++) {                                          \
                uint32_t ro = roff0 + i * 16;                                      \
                cpa16(db + ro,          gAh + (kc + 1) * 4 + i);                   \
                cpa16(db + 10240u + ro, gAl + (kc + 1) * 4 + i);                   \
                cpa16(db + 20480u + ro, gBh + (kc + 1) * 4 + i);                   \
                cpa16(db + 30720u + ro, gBl + (kc + 1) * 4 + i);                   \
            }                                                                      \
            asm volatile("cp.async.commit_group;" ::: "memory");                   \
            asm volatile("cp.async.wait_group 1;" ::: "memory");                   \
        } else {                                                                   \
            asm volatile("cp.async.wait_group 0;" ::: "memory");                   \
        }                                                                          \
        __syncthreads();                                                           \
        uint32_t sb = smb + (uint32_t)(kc & 1) * 40960u + lmoff;                   \
        _Pragma("unroll")                                                          \
        for (int k16 = 0; k16 < 2; k16++) {                                        \
            uint32_t kb = k16 * 32;                                                \
            uint32_t ah[2][4], al[2][4];                                           \
            _Pragma("unroll")                                                      \
            for (int mf = 0; mf < 2; mf++) {                                       \
                uint32_t off = (uint32_t)((wm + mf * 16) * 80) + kb;               \
                LDSM4(ah[mf][0], ah[mf][1], ah[mf][2], ah[mf][3], sb + off);       \
                LDSM4(al[mf][0], al[mf][1], al[mf][2], al[mf][3], sb + 10240u + off); \
            }                                                                      \
            _Pragma("unroll")                                                      \
            for (int g = 0; g < 4; g++) {                                          \
                uint32_t off = (uint32_t)((wn + g * 16) * 80) + kb;                \
                uint32_t bh0, bh1, bh2, bh3, bl0, bl1, bl2, bl3;                   \
                LDSM4(bh0, bh1, bh2, bh3, sb + 20480u + off);                      \
                LDSM4(bl0, bl1, bl2, bl3, sb + 30720u + off);                      \
                _Pragma("unroll")                                                  \
                for (int mf = 0; mf < 2; mf++) {                                   \
                    MMA16816(acc[mf][g * 2],     ah[mf], bh0, bh2);                \
                    MMA16816(acc[mf][g * 2 + 1], ah[mf], bh1, bh3);                \
                    MMA16816(acc[mf][g * 2],     ah[mf], bl0, bl2);                \
                    MMA16816(acc[mf][g * 2 + 1], ah[mf], bl1, bl3);                \
                    MMA16816(acc[mf][g * 2],     al[mf], bh0, bh2);                \
                    MMA16816(acc[mf][g * 2 + 1], al[mf], bh1, bh3);                \
                }                                                                  \
            }                                                                      \
        }                                                                          \
        __syncthreads();                                                           \
    }

// classifier: out = P @ Wc + bc
__global__ __launch_bounds__(256) void k_clf(const float* __restrict__ bias,
                                             float* __restrict__ out) {
    int n0 = blockIdx.x * 128, m0 = blockIdx.y * 128;
    HMMA_BODY(d_Ph, d_Pl, d_WcTh, d_WcTl)
    #pragma unroll
    for (int mf = 0; mf < 2; mf++) {
        int m = m0 + wm + mf * 16 + (lane >> 2);
        float* o0 = out + (size_t)m * VV;
        float* o1 = out + (size_t)(m + 8) * VV;
        #pragma unroll
        for (int nf = 0; nf < 8; nf++) {
            int n = n0 + wn + nf * 8 + (lane & 3) * 2;
            float b0v = bias[n], b1v = bias[n + 1];
            float2 v0, v1;
            v0.x = acc[mf][nf][0] + b0v; v0.y = acc[mf][nf][1] + b1v;
            v1.x = acc[mf][nf][2] + b0v; v1.y = acc[mf][nf][3] + b1v;
            *(float2*)(o0 + n) = v0;
            *(float2*)(o1 + n) = v1;
        }
    }
}

// Ux: Uxp[(step*NG+colp)*32+b] = Xall @ U0T^T + cb0p, rows r = step*32+b
__global__ __launch_bounds__(256) void k_ux() {
    int n0 = blockIdx.x * 128, m0 = blockIdx.y * 128;
    HMMA_BODY(d_Xh, d_Xl, d_U0Th, d_U0Tl)
    #pragma unroll
    for (int mf = 0; mf < 2; mf++) {
        int r0 = m0 + wm + mf * 16 + (lane >> 2);
        int r1 = r0 + 8;
        int s0 = r0 >> 5, bb0 = r0 & 31;
        int s1 = r1 >> 5, bb1 = r1 & 31;
        #pragma unroll
        for (int nf = 0; nf < 8; nf++) {
            int n = n0 + wn + nf * 8 + (lane & 3) * 2;
            float b0v = d_cb0p[n], b1v = d_cb0p[n + 1];
            d_Uxp[((size_t)s0 * NG + n) * 32 + bb0]       = acc[mf][nf][0] + b0v;
            d_Uxp[((size_t)s0 * NG + n + 1) * 32 + bb0]   = acc[mf][nf][1] + b1v;
            d_Uxp[((size_t)s1 * NG + n) * 32 + bb1]       = acc[mf][nf][2] + b0v;
            d_Uxp[((size_t)s1 * NG + n + 1) * 32 + bb1]   = acc[mf][nf][3] + b1v;
        }
    }
}

// ---------------- launch --------------------------------------------------------

extern "C" void kernel_launch(void* const* d_in, const int* in_sizes, int n_in,
                              void* d_out, int out_size) {
    const float* im    = (const float*)d_in[0];
    const int*   tok   = (const int*)  d_in[1];
    const float* h0    = (const float*)d_in[2];
    const float* c0    = (const float*)d_in[3];
    const float* embed = (const float*)d_in[4];
    const float* W_im  = (const float*)d_in[5];
    const float* b_im  = (const float*)d_in[6];
    const float* Wh    = (const float*)d_in[7];
    const float* bw    = (const float*)d_in[8];
    const float* Uh    = (const float*)d_in[9];
    const float* bu    = (const float*)d_in[10];
    const float* Wxh   = (const float*)d_in[11];
    const float* bxh   = (const float*)d_in[12];
    const float* Wc    = (const float*)d_in[13];
    const float* bc    = (const float*)d_in[14];
    float* out = (float*)d_out;

    float *pM, *pMp, *pWp0, *pWp1, *pHs;
    __nv_bfloat16 *pPh, *pPl;
    cudaGetSymbolAddress((void**)&pM,    d_M);
    cudaGetSymbolAddress((void**)&pMp,   d_Mp);
    cudaGetSymbolAddress((void**)&pWp0,  d_Wp0);
    cudaGetSymbolAddress((void**)&pWp1,  d_Wp1);
    cudaGetSymbolAddress((void**)&pHs,   d_Hs);
    cudaGetSymbolAddress((void**)&pPh,   d_Ph);
    cudaGetSymbolAddress((void**)&pPl,   d_Pl);

    cudaFuncSetAttribute(k_recur, cudaFuncAttributeMaxDynamicSharedMemorySize, RECUR_SMEM);
    cudaFuncSetAttribute(k_clf,   cudaFuncAttributeMaxDynamicSharedMemorySize, HMMA_SMEM);
    cudaFuncSetAttribute(k_ux,    cudaFuncAttributeMaxDynamicSharedMemorySize, HMMA_SMEM);

    // ---- setup ----
    k_ximg    <<<64, 256>>>(im, W_im, b_im);
    k_gather  <<<4096, 128>>>(tok, embed);
    k_zero_pad<<<192, 256>>>();
    k_cvtX    <<<8448, 256>>>();
    k_cvtU0T  <<<4096, 256>>>(Uh);
    k_cb0p    <<<8, 256>>>(bw, bu);
    k_init    <<<64, 256>>>(h0, c0);
    k_cb1p    <<<8, 256>>>(bw, bu, bxh, Uh);
    k_permW   <<<4096, 256>>>(Wh, pWp0);
    k_permW   <<<4096, 256>>>(Wh + (size_t)HH * NG, pWp1);

    // M = Wxh0 @ Uh1, then permute
    k_sgemm<<<dim3(16, 4), 256>>>(Wxh, Uh + (size_t)HH * NG, pM, NG, DD, nullptr, 0,
                                  nullptr, nullptr);
    k_permW<<<4096, 256>>>(pM, pMp);

    // Uxp via split-bf16 HMMA  [4224,512] @ [512,2048]
    k_ux<<<dim3(16, 33), 256, HMMA_SMEM>>>();

    // ---- whole recurrence: single persistent kernel ----
    k_recur<<<RECUR_BLOCKS, 256, RECUR_SMEM>>>();

    // P = Hs @ Wxh1 + bxh1, split bf16 hi/lo
    k_sgemm<<<dim3(4, 32), 256>>>(pHs, Wxh + (size_t)HH * DD, nullptr, DD, DD,
                                  bxh + DD, 3, pPh, pPl);

    // Wc transpose+split (independent of recurrence path)
    k_cvtWc<<<dim3(1000, 16), 256>>>(Wc);

    // logits = P @ Wc + bc on tensor cores (split precision)
    k_clf<<<dim3(250, 32), 256, HMMA_SMEM>>>(bc, out);
}